// round 6
// baseline (speedup 1.0000x reference)
#include <cuda_runtime.h>

// Problem constants (fixed by reference_code)
#define LSEQ 8192
#define BATCH 32
#define CIN 7
#define KER 73            // 512 // 7
#define DM 512
#define RT 16             // output rows per tile
#define SL 64             // rows per block strip
#define TILES (SL / RT)   // 4
#define WROWS (SL + RT + 1)   // 81 window rows: strip + 16 back + 1 fwd
#define WELEMS (WROWS * CIN)  // 567

// out[b, n, c*73+k] = conv_b[k] + sum_{j=0..17} W2[k][j] * x[b, n+1-j, c]
//   W2[k][j] = conv_w[k][ (j/3)*3 + (2 - j%3) ]
// Conv position p = n-1+t contributes only if (after circular wrap) p >= 15.
// Interior rows 16..L-2 are unconditionally valid (fast path).

__global__ __launch_bounds__(512, 2)
void tokemb_kernel(const float* __restrict__ x,
                   const float* __restrict__ conv_w,
                   const float* __restrict__ conv_b,
                   const float* __restrict__ left_w,
                   const float* __restrict__ left_b,
                   float* __restrict__ out)
{
    const int d  = threadIdx.x;          // output channel 0..511
    const int s0 = blockIdx.x * SL;      // strip start row
    const int b  = blockIdx.y;

    // Per-thread channel / weights / bias (loaded ONCE per block)
    const bool main_ch = (d < CIN * KER);            // d < 511
    const int  c    = main_ch ? (d / KER) : (CIN - 1);
    const float* wsrc = main_ch ? (conv_w + (d % KER) * 18) : left_w;
    const float bias  = main_ch ? conv_b[d % KER] : left_b[0];

    float w[18];
    #pragma unroll
    for (int j = 0; j < 18; ++j)
        w[j] = wsrc[(j / 3) * 3 + 2 - (j % 3)];

    const float* xb = x + (size_t)b * LSEQ * CIN;

    // Stage x[b, s0-16 .. s0+SL, :] into smem: 567 elements, 2 per thread
    // (second predicated), index-clamped. Clamped (junk) rows are only read
    // by slow-path strips, which bypass smem entirely.
    __shared__ float xs[WELEMS];
    {
        const int gbase = (s0 - RT) * CIN;    // may be negative at strip 0
        int g0 = gbase + d;
        g0 = min(max(g0, 0), LSEQ * CIN - 1);
        xs[d] = xb[g0];
        const int i1 = d + 512;
        if (i1 < WELEMS) {
            int g1 = gbase + i1;
            g1 = min(max(g1, 0), LSEQ * CIN - 1);
            xs[i1] = xb[g1];
        }
    }
    __syncthreads();

    float* outp = out + ((size_t)(b * LSEQ + s0)) * DM + d;

    // Uniform branch: only the first and last strip of each sequence contain
    // any invalid/wrapping rows.
    const bool strip_fast = (s0 >= 16) && (s0 + SL <= LSEQ - 1);

    if (strip_fast) {
        #pragma unroll
        for (int t = 0; t < TILES; ++t) {
            const float* xcol = xs + (t * RT) * CIN + c;
            float* op = outp + t * RT * DM;

            float acc[RT];
            #pragma unroll
            for (int nl = 0; nl < RT; ++nl) acc[nl] = bias;

            // Value-outer: each window value loaded once (LDS at immediate
            // offset), fanned into the accumulators it feeds.
            #pragma unroll
            for (int i = 0; i < RT + 17; ++i) {
                const float xv = xcol[i * CIN];
                #pragma unroll
                for (int j = 0; j < 18; ++j) {
                    const int nl = i + j - 17;   // output row fed by (i, j)
                    if (nl >= 0 && nl < RT)
                        acc[nl] = fmaf(w[j], xv, acc[nl]);
                }
            }

            #pragma unroll
            for (int nl = 0; nl < RT; ++nl)
                __stcs(op + nl * DM, acc[nl]);   // streaming store: keep x in L2
        }
    } else {
        // Generic path: explicit wrap + validity per conv tap. Only 2 strips
        // per batch row (64 / 4096 blocks) land here.
        for (int nl = 0; nl < SL; ++nl) {
            const int n = s0 + nl;
            float acc = bias;
            #pragma unroll
            for (int tt = 0; tt < 3; ++tt) {
                int p = n - 1 + tt;
                if (p < 0)      p += LSEQ;   // circular pad left
                if (p >= LSEQ)  p -= LSEQ;   // circular pad right
                if (p >= 15) {               // delay-embedding validity (M*TAO)
                    #pragma unroll
                    for (int m = 0; m < 6; ++m)
                        acc = fmaf(w[3 * m + 2 - tt],
                                   xb[(p - 3 * m) * CIN + c], acc);
                }
            }
            __stcs(outp + nl * DM, acc);
        }
    }
}

extern "C" void kernel_launch(void* const* d_in, const int* in_sizes, int n_in,
                              void* d_out, int out_size)
{
    const float* x      = (const float*)d_in[0];
    const float* conv_w = (const float*)d_in[1];
    const float* conv_b = (const float*)d_in[2];
    const float* left_w = (const float*)d_in[3];
    const float* left_b = (const float*)d_in[4];
    float* out = (float*)d_out;

    dim3 grid(LSEQ / SL, BATCH);   // (128, 32) = 4096 blocks
    tokemb_kernel<<<grid, 512>>>(x, conv_w, conv_b, left_w, left_b, out);
}